// round 13
// baseline (speedup 1.0000x reference)
#include <cuda_runtime.h>

// Problem constants
#define BSZ   4096
#define PSZ   32
#define EMB   128
#define HDIM  768
#define MROWS 16            // batch rows per MLP block

// Scratch: intermediate H [B, 768] (12.6 MB)
__device__ float g_H[BSZ * HDIM];

__device__ __forceinline__ float4 relu_step(float4 x, float4 w, float4 y, float4 bm) {
    float4 r;
    r.x = fmaxf(fmaf(x.x * w.x, y.x, bm.x), 0.f);
    r.y = fmaxf(fmaf(x.y * w.y, y.y, bm.y), 0.f);
    r.z = fmaxf(fmaf(x.z * w.z, y.z, bm.z), 0.f);
    r.w = fmaxf(fmaf(x.w * w.w, y.w, bm.w), 0.f);
    return r;
}

// Warp-uniform 3-way select of a float4 register triple.
__device__ __forceinline__ float4 sel3(int mi, float4 a, float4 b, float4 c) {
    float4 r;
    r.x = (mi == 0) ? a.x : (mi == 1) ? b.x : c.x;
    r.y = (mi == 0) ? a.y : (mi == 1) ? b.y : c.y;
    r.z = (mi == 0) ? a.z : (mi == 1) ? b.z : c.z;
    r.w = (mi == 0) ? a.w : (mi == 1) ? b.w : c.w;
    return r;
}

struct PathSmem {
    float sAcc[8][256];
    float sCnt[8];
};

// One block per (batch row b, group). 8 warps; warp w handles paths
// p = w, w+8, w+16, w+24 with 1-path lookahead prefetch of embedding rows.
// W/Bm metapath params live in per-thread REGISTERS (3 rows each); the
// per-step selection is warp-uniform and done once, reused fwd+bwd.
template<int L>
__device__ __forceinline__ void path_body(
    PathSmem& sm,
    const int*   __restrict__ ents,    // [B,P,L+1]
    const int*   __restrict__ mids,    // [B,P,L]
    const float* __restrict__ counts,  // [B,P]
    const float* __restrict__ E,       // [100000,128]
    const float* __restrict__ Wm,      // [3,128]
    const float* __restrict__ Bm,      // [3,128]
    int gofs)
{
    const int b    = blockIdx.x;
    const int tid  = threadIdx.x;
    const int wid  = tid >> 5;
    const int lane = tid & 31;
    const int lo   = lane * 4;

    // All metapath params in registers (lane owns dims [4*lane,4*lane+4)).
    const float4 w0 = *(const float4*)(Wm + 0 * EMB + lo);
    const float4 w1 = *(const float4*)(Wm + 1 * EMB + lo);
    const float4 w2 = *(const float4*)(Wm + 2 * EMB + lo);
    const float4 q0 = *(const float4*)(Bm + 0 * EMB + lo);
    const float4 q1 = *(const float4*)(Bm + 1 * EMB + lo);
    const float4 q2 = *(const float4*)(Bm + 2 * EMB + lo);

    // Hoist indices + counts for this warp's 4 paths (warp-uniform loads)
    int   e[4][L + 1];
    int   m[4][L];
    float cnt[4];
    #pragma unroll
    for (int pp = 0; pp < 4; pp++) {
        const long base = (long)b * PSZ + (wid + pp * 8);
        const int* ep = ents + base * (L + 1);
        const int* mp = mids + base * L;
        #pragma unroll
        for (int i = 0; i <= L; i++) e[pp][i] = ep[i];
        #pragma unroll
        for (int i = 0; i < L; i++)  m[pp][i] = mp[i];
        cnt[pp] = counts[base];
    }

    float4 a1 = make_float4(0.f, 0.f, 0.f, 0.f);
    float4 a2 = make_float4(0.f, 0.f, 0.f, 0.f);
    float  cs = 0.f;

    // Double-buffered embedding-row gathers: buf[pp&1] = rows of path pp
    float4 buf[2][L + 1];
    #pragma unroll
    for (int i = 0; i <= L; i++)
        buf[0][i] = *(const float4*)(E + (long)e[0][i] * EMB + lo);

    #pragma unroll
    for (int pp = 0; pp < 4; pp++) {
        if (pp < 3) {
            #pragma unroll
            for (int i = 0; i <= L; i++)
                buf[(pp + 1) & 1][i] =
                    *(const float4*)(E + (long)e[pp + 1][i] * EMB + lo);
        }
        float4 (&rows)[L + 1] = buf[pp & 1];

        // Select W/Bm registers once per step (warp-uniform), reuse fwd+bwd.
        float4 ws[L], bs[L];
        #pragma unroll
        for (int i = 0; i < L; i++) {
            const int mi = m[pp][i];
            ws[i] = sel3(mi, w0, w1, w2);
            bs[i] = sel3(mi, q0, q1, q2);
        }

        // forward
        float4 x = rows[0];
        #pragma unroll
        for (int i = 0; i < L; i++)
            x = relu_step(x, ws[i], rows[i + 1], bs[i]);
        const float4 o1 = x;

        // backward: start x and (stale) y are both E[ents[L]]
        const float4 yl = rows[L];
        x = yl;
        #pragma unroll
        for (int i = L - 1; i >= 0; i--)
            x = relu_step(x, ws[i], yl, bs[i]);

        const float c0 = cnt[pp];
        a1.x += c0 * o1.x; a1.y += c0 * o1.y; a1.z += c0 * o1.z; a1.w += c0 * o1.w;
        a2.x += c0 * x.x;  a2.y += c0 * x.y;  a2.z += c0 * x.z;  a2.w += c0 * x.w;
        cs   += c0;
    }

    ((float4*)sm.sAcc[wid])[lane]         = a1;   // dims 0..127
    ((float4*)(sm.sAcc[wid] + 128))[lane] = a2;   // dims 128..255
    if (lane == 0) sm.sCnt[wid] = cs;
    __syncthreads();

    // Deterministic reduce across the 8 warps
    float s = 0.f, csum = 0.f;
    #pragma unroll
    for (int w = 0; w < 8; w++) { s += sm.sAcc[w][tid]; csum += sm.sCnt[w]; }
    g_H[(long)b * HDIM + gofs + tid] = s / csum;
}

__global__ __launch_bounds__(256, 2) void paths_kernel(
    const int* __restrict__ ent1, const int* __restrict__ mid1, const float* __restrict__ c1,
    const int* __restrict__ ent2, const int* __restrict__ mid2, const float* __restrict__ c2,
    const int* __restrict__ ent3, const int* __restrict__ mid3, const float* __restrict__ c3,
    const float* __restrict__ E, const float* __restrict__ Wm, const float* __restrict__ Bm)
{
    __shared__ PathSmem sm;
    const int g = blockIdx.y;
    if (g == 0)      path_body<1>(sm, ent1, mid1, c1, E, Wm, Bm, 0);
    else if (g == 1) path_body<2>(sm, ent2, mid2, c2, E, Wm, Bm, 256);
    else             path_body<3>(sm, ent3, mid3, c3, E, Wm, Bm, 512);
}

// ────────────────────────────────────────────────────────────────────────
// MLP head (R4 plain-fp32 — best by end-to-end timing):
// 16 rows/block, 512 threads, 256 blocks.
// ────────────────────────────────────────────────────────────────────────
__global__ __launch_bounds__(512) void mlp_kernel(
    const float* __restrict__ W1, const float* __restrict__ b1,
    const float* __restrict__ W2, const float* __restrict__ b2,
    const float* __restrict__ W3, const float* __restrict__ b3,
    float* __restrict__ out)
{
    __shared__ float smem[MROWS * HDIM];        // 48 KB
    float* const sH = smem;

    const int b0  = blockIdx.x * MROWS;
    const int tid = threadIdx.x;

    // Load full H tile (3072 float4, 6 per thread)
    {
        const float4* src = (const float4*)(g_H + (long)b0 * HDIM);
        float4*       dst = (float4*)sH;
        #pragma unroll
        for (int i = 0; i < (MROWS * HDIM / 4) / 512; i++)
            dst[tid + i * 512] = src[tid + i * 512];
    }
    __syncthreads();

    // ── Phase A: h1 = relu(H @ W1 + b1), [16,128] ────────────────────────
    const int c     = tid & 127;
    const int rbase = (tid >> 7) * 4;     // 0,4,8,12
    float acc[4];
    {
        const float bias1 = b1[c];
        #pragma unroll
        for (int r = 0; r < 4; r++) acc[r] = bias1;
    }

    #pragma unroll 4
    for (int kb = 0; kb < HDIM; kb += 4) {
        const float* wp = W1 + kb * 128 + c;
        const float w0 = __ldg(wp);
        const float w1 = __ldg(wp + 128);
        const float w2 = __ldg(wp + 256);
        const float w3 = __ldg(wp + 384);
        #pragma unroll
        for (int r = 0; r < 4; r++) {
            const float4 h = *(const float4*)(sH + (rbase + r) * HDIM + kb);
            float a = acc[r];
            a = fmaf(h.x, w0, a);
            a = fmaf(h.y, w1, a);
            a = fmaf(h.z, w2, a);
            a = fmaf(h.w, w3, a);
            acc[r] = a;
        }
    }
    __syncthreads();          // everyone done reading sH

    float* const sh1 = smem;                 // [16][128]
    float* const sh2 = smem + MROWS * 128;   // [16][32]
    #pragma unroll
    for (int r = 0; r < 4; r++)
        sh1[(rbase + r) * 128 + c] = fmaxf(acc[r], 0.f);
    __syncthreads();

    // ── Phase B: h2 = relu(h1 @ W2 + b2), [16,32] — 512 thr = 16r × 32c ──
    {
        const int c2 = tid & 31;
        const int r  = tid >> 5;   // 0..15
        float a = b2[c2];
        #pragma unroll 8
        for (int k = 0; k < 128; k += 4) {
            const float4 h = *(const float4*)(sh1 + r * 128 + k);
            a = fmaf(h.x, __ldg(W2 + (k    ) * 32 + c2), a);
            a = fmaf(h.y, __ldg(W2 + (k + 1) * 32 + c2), a);
            a = fmaf(h.z, __ldg(W2 + (k + 2) * 32 + c2), a);
            a = fmaf(h.w, __ldg(W2 + (k + 3) * 32 + c2), a);
        }
        sh2[r * 32 + c2] = fmaxf(a, 0.f);
    }
    __syncthreads();

    // ── Phase C: out = h2 @ W3 + b3, [16,1] ─────────────────────────────
    if (tid < MROWS) {
        float a = b3[0];
        #pragma unroll
        for (int k = 0; k < 32; k++) a = fmaf(sh2[tid * 32 + k], W3[k], a);
        out[b0 + tid] = a;
    }
}

extern "C" void kernel_launch(void* const* d_in, const int* in_sizes, int n_in,
                              void* d_out, int out_size)
{
    const bool dictOrder = (in_sizes[2] == BSZ * PSZ);

    const int *ent1, *mid1, *ent2, *mid2, *ent3, *mid3;
    const float *c1, *c2, *c3;
    if (dictOrder) {
        ent1 = (const int*)d_in[0]; mid1 = (const int*)d_in[1]; c1 = (const float*)d_in[2];
        ent2 = (const int*)d_in[3]; mid2 = (const int*)d_in[4]; c2 = (const float*)d_in[5];
        ent3 = (const int*)d_in[6]; mid3 = (const int*)d_in[7]; c3 = (const float*)d_in[8];
    } else {
        ent1 = (const int*)d_in[0]; mid1 = (const int*)d_in[1];
        ent2 = (const int*)d_in[2]; mid2 = (const int*)d_in[3];
        ent3 = (const int*)d_in[4]; mid3 = (const int*)d_in[5];
        c1 = (const float*)d_in[6]; c2 = (const float*)d_in[7]; c3 = (const float*)d_in[8];
    }
    const float* E  = (const float*)d_in[9];
    const float* Wm = (const float*)d_in[10];
    const float* Bm = (const float*)d_in[11];
    const float* W1 = (const float*)d_in[12];
    const float* b1 = (const float*)d_in[13];
    const float* W2 = (const float*)d_in[14];
    const float* b2 = (const float*)d_in[15];
    const float* W3 = (const float*)d_in[16];
    const float* b3 = (const float*)d_in[17];

    dim3 pgrid(BSZ, 3);
    paths_kernel<<<pgrid, 256>>>(ent1, mid1, c1, ent2, mid2, c2, ent3, mid3, c3,
                                 E, Wm, Bm);
    mlp_kernel<<<BSZ / MROWS, 512>>>(W1, b1, W2, b2, W3, b3, (float*)d_out);
}

// round 14
// speedup vs baseline: 1.0224x; 1.0224x over previous
#include <cuda_runtime.h>

// Problem constants
#define BSZ   4096
#define PSZ   32
#define EMB   128
#define HDIM  768
#define MBLK  32            // batch rows per MLP block (tensor-core version)

// Scratch: intermediate H [B, 768] (12.6 MB)
__device__ float g_H[BSZ * HDIM];

__device__ __forceinline__ float4 relu_step(float4 x, float4 w, float4 y, float4 bm) {
    float4 r;
    r.x = fmaxf(fmaf(x.x * w.x, y.x, bm.x), 0.f);
    r.y = fmaxf(fmaf(x.y * w.y, y.y, bm.y), 0.f);
    r.z = fmaxf(fmaf(x.z * w.z, y.z, bm.z), 0.f);
    r.w = fmaxf(fmaf(x.w * w.w, y.w, bm.w), 0.f);
    return r;
}

struct PathSmem {
    float sW[3 * EMB];
    float sB[3 * EMB];
    float sAcc[8][256];
    float sCnt[8];
};

// ── paths kernel: exact R4 version (best measured; do not touch) ────────
template<int L>
__device__ __forceinline__ void path_body(
    PathSmem& sm,
    const int*   __restrict__ ents,
    const int*   __restrict__ mids,
    const float* __restrict__ counts,
    const float* __restrict__ E,
    const float* __restrict__ Wm,
    const float* __restrict__ Bm,
    int gofs)
{
    const int b    = blockIdx.x;
    const int tid  = threadIdx.x;
    const int wid  = tid >> 5;
    const int lane = tid & 31;

    for (int i = tid; i < 3 * EMB; i += 256) { sm.sW[i] = Wm[i]; sm.sB[i] = Bm[i]; }
    __syncthreads();

    int   e[4][L + 1];
    int   m[4][L];
    float cnt[4];
    #pragma unroll
    for (int pp = 0; pp < 4; pp++) {
        const long base = (long)b * PSZ + (wid + pp * 8);
        const int* ep = ents + base * (L + 1);
        const int* mp = mids + base * L;
        #pragma unroll
        for (int i = 0; i <= L; i++) e[pp][i] = ep[i];
        #pragma unroll
        for (int i = 0; i < L; i++)  m[pp][i] = mp[i];
        cnt[pp] = counts[base];
    }

    float4 a1 = make_float4(0.f, 0.f, 0.f, 0.f);
    float4 a2 = make_float4(0.f, 0.f, 0.f, 0.f);
    float  cs = 0.f;

    float4 buf[2][L + 1];
    #pragma unroll
    for (int i = 0; i <= L; i++)
        buf[0][i] = *(const float4*)(E + (long)e[0][i] * EMB + lane * 4);

    #pragma unroll
    for (int pp = 0; pp < 4; pp++) {
        if (pp < 3) {
            #pragma unroll
            for (int i = 0; i <= L; i++)
                buf[(pp + 1) & 1][i] =
                    *(const float4*)(E + (long)e[pp + 1][i] * EMB + lane * 4);
        }
        float4 (&rows)[L + 1] = buf[pp & 1];

        float4 x = rows[0];
        #pragma unroll
        for (int i = 0; i < L; i++) {
            float4 w  = *(const float4*)(sm.sW + m[pp][i] * EMB + lane * 4);
            float4 bb = *(const float4*)(sm.sB + m[pp][i] * EMB + lane * 4);
            x = relu_step(x, w, rows[i + 1], bb);
        }
        const float4 o1 = x;

        const float4 yl = rows[L];
        x = yl;
        #pragma unroll
        for (int i = L - 1; i >= 0; i--) {
            float4 w  = *(const float4*)(sm.sW + m[pp][i] * EMB + lane * 4);
            float4 bb = *(const float4*)(sm.sB + m[pp][i] * EMB + lane * 4);
            x = relu_step(x, w, yl, bb);
        }

        const float c0 = cnt[pp];
        a1.x += c0 * o1.x; a1.y += c0 * o1.y; a1.z += c0 * o1.z; a1.w += c0 * o1.w;
        a2.x += c0 * x.x;  a2.y += c0 * x.y;  a2.z += c0 * x.z;  a2.w += c0 * x.w;
        cs   += c0;
    }

    ((float4*)sm.sAcc[wid])[lane]         = a1;
    ((float4*)(sm.sAcc[wid] + 128))[lane] = a2;
    if (lane == 0) sm.sCnt[wid] = cs;
    __syncthreads();

    float s = 0.f, csum = 0.f;
    #pragma unroll
    for (int w = 0; w < 8; w++) { s += sm.sAcc[w][tid]; csum += sm.sCnt[w]; }
    g_H[(long)b * HDIM + gofs + tid] = s / csum;
}

__global__ __launch_bounds__(256) void paths_kernel(
    const int* __restrict__ ent1, const int* __restrict__ mid1, const float* __restrict__ c1,
    const int* __restrict__ ent2, const int* __restrict__ mid2, const float* __restrict__ c2,
    const int* __restrict__ ent3, const int* __restrict__ mid3, const float* __restrict__ c3,
    const float* __restrict__ E, const float* __restrict__ Wm, const float* __restrict__ Bm)
{
    __shared__ PathSmem sm;
    const int g = blockIdx.y;
    if (g == 0)      path_body<1>(sm, ent1, mid1, c1, E, Wm, Bm, 0);
    else if (g == 1) path_body<2>(sm, ent2, mid2, c2, E, Wm, Bm, 256);
    else             path_body<3>(sm, ent3, mid3, c3, E, Wm, Bm, 512);
}

// ────────────────────────────────────────────────────────────────────────
// MLP head, tensor-core version.
// Layer 1 as tf32 mma.sync.m16n8k8 GEMM: 128 blocks × 32 rows, 256 thr.
// K streamed in 6 chunks of 128 through padded smem (Hc stride 132,
// Wc stride 136 → conflict-free fragment loads). Layers 2/3 in fp32.
// ────────────────────────────────────────────────────────────────────────
#define HC_STRIDE 132
#define WC_STRIDE 136
#define SB_F      164                       // sb1[128], sb2[32], sb3[1], pad
#define HC_F      (MBLK * HC_STRIDE)        // 4224
#define WC_F      (128 * WC_STRIDE)         // 17408
#define MLP_SMEM_F (SB_F + HC_F + WC_F)     // 21796 floats = 87184 B

extern __shared__ float dsm[];

__device__ __forceinline__ float totf32(float x) {
    unsigned int u;
    asm("cvt.rna.tf32.f32 %0, %1;" : "=r"(u) : "f"(x));
    return __uint_as_float(u);
}

__device__ __forceinline__ void mma_tf32(float c[4],
    unsigned int a0, unsigned int a1, unsigned int a2, unsigned int a3,
    unsigned int b0, unsigned int b1)
{
    asm volatile(
        "mma.sync.aligned.m16n8k8.row.col.f32.tf32.tf32.f32 "
        "{%0,%1,%2,%3}, {%4,%5,%6,%7}, {%8,%9}, {%0,%1,%2,%3};"
        : "+f"(c[0]), "+f"(c[1]), "+f"(c[2]), "+f"(c[3])
        : "r"(a0), "r"(a1), "r"(a2), "r"(a3), "r"(b0), "r"(b1));
}

__global__ __launch_bounds__(256) void mlp_kernel(
    const float* __restrict__ W1, const float* __restrict__ b1,
    const float* __restrict__ W2, const float* __restrict__ b2,
    const float* __restrict__ W3, const float* __restrict__ b3,
    float* __restrict__ out)
{
    float* const sb1 = dsm;            // [128]
    float* const sb2 = dsm + 128;      // [32]
    float* const sb3 = dsm + 160;      // [1]
    float* const Hc  = dsm + SB_F;     // [32][132]
    float* const Wc  = Hc + HC_F;      // [128][136]

    const int b0   = blockIdx.x * MBLK;
    const int tid  = threadIdx.x;
    const int lane = tid & 31;
    const int wrp  = tid >> 5;         // 0..7, owns cols [16w,16w+16)
    const int gid  = lane >> 2;        // 0..7
    const int tig  = lane & 3;         // 0..3

    // Stage biases once
    if (tid < 128) sb1[tid] = b1[tid];
    if (tid < 32)  sb2[tid] = b2[tid];
    if (tid == 0)  sb3[0]   = b3[0];

    float acc[2][2][4];
    #pragma unroll
    for (int mt = 0; mt < 2; mt++)
        #pragma unroll
        for (int nt = 0; nt < 2; nt++)
            #pragma unroll
            for (int i = 0; i < 4; i++) acc[mt][nt][i] = 0.f;

    // ── Phase A: K-chunked tf32 GEMM ────────────────────────────────────
    for (int kc = 0; kc < HDIM; kc += 128) {
        if (kc) __syncthreads();       // previous chunk's reads complete

        // Stage Hc [32][128] (4 float4/thread) with tf32 rounding
        #pragma unroll
        for (int j = 0; j < 4; j++) {
            const int i   = tid + j * 256;
            const int row = i >> 5, c4 = i & 31;
            float4 v = *(const float4*)(g_H + (long)(b0 + row) * HDIM + kc + c4 * 4);
            v.x = totf32(v.x); v.y = totf32(v.y); v.z = totf32(v.z); v.w = totf32(v.w);
            *(float4*)(Hc + row * HC_STRIDE + c4 * 4) = v;
        }
        // Stage Wc [128][128] (16 float4/thread) with tf32 rounding
        #pragma unroll
        for (int j = 0; j < 16; j++) {
            const int i  = tid + j * 256;
            const int kr = i >> 5, c4 = i & 31;
            float4 v = *(const float4*)(W1 + (long)(kc + kr) * 128 + c4 * 4);
            v.x = totf32(v.x); v.y = totf32(v.y); v.z = totf32(v.z); v.w = totf32(v.w);
            *(float4*)(Wc + kr * WC_STRIDE + c4 * 4) = v;
        }
        __syncthreads();

        #pragma unroll
        for (int kk = 0; kk < 16; kk++) {
            const int kb = kk * 8 + tig;
            unsigned int A0[2], A1[2], A2[2], A3[2];
            #pragma unroll
            for (int mt = 0; mt < 2; mt++) {
                const float* ap  = Hc + (mt * 16 + gid) * HC_STRIDE + kb;
                const float* ap8 = ap + 8 * HC_STRIDE;
                A0[mt] = __float_as_uint(ap[0]);
                A2[mt] = __float_as_uint(ap[4]);
                A1[mt] = __float_as_uint(ap8[0]);
                A3[mt] = __float_as_uint(ap8[4]);
            }
            #pragma unroll
            for (int nt = 0; nt < 2; nt++) {
                const int n = wrp * 16 + nt * 8 + gid;
                const unsigned int B0 = __float_as_uint(Wc[kb * WC_STRIDE + n]);
                const unsigned int B1 = __float_as_uint(Wc[(kb + 4) * WC_STRIDE + n]);
                mma_tf32(acc[0][nt], A0[0], A1[0], A2[0], A3[0], B0, B1);
                mma_tf32(acc[1][nt], A0[1], A1[1], A2[1], A3[1], B0, B1);
            }
        }
    }
    __syncthreads();                   // all compute done; Hc/Wc reusable

    // Epilogue: bias + relu → sh1 [32][132] (overlays Hc)
    float* const sh1 = Hc;
    float* const sh2 = Wc;             // [32][33]
    #pragma unroll
    for (int mt = 0; mt < 2; mt++) {
        #pragma unroll
        for (int nt = 0; nt < 2; nt++) {
            const int n0 = wrp * 16 + nt * 8 + tig * 2;
            const int rl = mt * 16 + gid, rh = rl + 8;
            sh1[rl * HC_STRIDE + n0]     = fmaxf(acc[mt][nt][0] + sb1[n0],     0.f);
            sh1[rl * HC_STRIDE + n0 + 1] = fmaxf(acc[mt][nt][1] + sb1[n0 + 1], 0.f);
            sh1[rh * HC_STRIDE + n0]     = fmaxf(acc[mt][nt][2] + sb1[n0],     0.f);
            sh1[rh * HC_STRIDE + n0 + 1] = fmaxf(acc[mt][nt][3] + sb1[n0 + 1], 0.f);
        }
    }
    __syncthreads();

    // ── Phase B: h2 = relu(h1 @ W2 + b2), [32,32] fp32 ──────────────────
    {
        const int r  = tid >> 3;           // 0..31
        const int cb = (tid & 7) * 4;      // 0,4,...,28
        float a0 = sb2[cb], a1 = sb2[cb + 1], a2 = sb2[cb + 2], a3 = sb2[cb + 3];
        #pragma unroll 8
        for (int k = 0; k < 128; k++) {
            const float  h = sh1[r * HC_STRIDE + k];
            const float4 w = *(const float4*)(W2 + k * 32 + cb);
            a0 = fmaf(h, w.x, a0);
            a1 = fmaf(h, w.y, a1);
            a2 = fmaf(h, w.z, a2);
            a3 = fmaf(h, w.w, a3);
        }
        sh2[r * 33 + cb]     = fmaxf(a0, 0.f);
        sh2[r * 33 + cb + 1] = fmaxf(a1, 0.f);
        sh2[r * 33 + cb + 2] = fmaxf(a2, 0.f);
        sh2[r * 33 + cb + 3] = fmaxf(a3, 0.f);
    }
    __syncthreads();

    // ── Phase C: out = h2 @ W3 + b3, [32,1] fp32 ────────────────────────
    if (tid < MBLK) {
        float a = sb3[0];
        #pragma unroll
        for (int k = 0; k < 32; k++) a = fmaf(sh2[tid * 33 + k], W3[k], a);
        out[b0 + tid] = a;
    }
}

extern "C" void kernel_launch(void* const* d_in, const int* in_sizes, int n_in,
                              void* d_out, int out_size)
{
    const bool dictOrder = (in_sizes[2] == BSZ * PSZ);

    const int *ent1, *mid1, *ent2, *mid2, *ent3, *mid3;
    const float *c1, *c2, *c3;
    if (dictOrder) {
        ent1 = (const int*)d_in[0]; mid1 = (const int*)d_in[1]; c1 = (const float*)d_in[2];
        ent2 = (const int*)d_in[3]; mid2 = (const int*)d_in[4]; c2 = (const float*)d_in[5];
        ent3 = (const int*)d_in[6]; mid3 = (const int*)d_in[7]; c3 = (const float*)d_in[8];
    } else {
        ent1 = (const int*)d_in[0]; mid1 = (const int*)d_in[1];
        ent2 = (const int*)d_in[2]; mid2 = (const int*)d_in[3];
        ent3 = (const int*)d_in[4]; mid3 = (const int*)d_in[5];
        c1 = (const float*)d_in[6]; c2 = (const float*)d_in[7]; c3 = (const float*)d_in[8];
    }
    const float* E  = (const float*)d_in[9];
    const float* Wm = (const float*)d_in[10];
    const float* Bm = (const float*)d_in[11];
    const float* W1 = (const float*)d_in[12];
    const float* b1 = (const float*)d_in[13];
    const float* W2 = (const float*)d_in[14];
    const float* b2 = (const float*)d_in[15];
    const float* W3 = (const float*)d_in[16];
    const float* b3 = (const float*)d_in[17];

    const int mlpSmem = MLP_SMEM_F * sizeof(float);   // 87184 B
    cudaFuncSetAttribute(mlp_kernel, cudaFuncAttributeMaxDynamicSharedMemorySize,
                         mlpSmem);

    dim3 pgrid(BSZ, 3);
    paths_kernel<<<pgrid, 256>>>(ent1, mid1, c1, ent2, mid2, c2, ent3, mid3, c3,
                                 E, Wm, Bm);
    mlp_kernel<<<BSZ / MBLK, 256, mlpSmem>>>(W1, b1, W2, b2, W3, b3, (float*)d_out);
}

// round 15
// speedup vs baseline: 1.3002x; 1.2718x over previous
#include <cuda_runtime.h>

// Problem constants
#define BSZ   4096
#define PSZ   32
#define EMB   128
#define HDIM  768
#define MBLK  16            // batch rows per MLP block

// Scratch: intermediate H [B, 768] (12.6 MB)
__device__ float g_H[BSZ * HDIM];
// tf32-rounded copy of W1 (768x128), written once per launch by w1cvt_kernel
__device__ float g_W1c[HDIM * 128];

__device__ __forceinline__ float4 relu_step(float4 x, float4 w, float4 y, float4 bm) {
    float4 r;
    r.x = fmaxf(fmaf(x.x * w.x, y.x, bm.x), 0.f);
    r.y = fmaxf(fmaf(x.y * w.y, y.y, bm.y), 0.f);
    r.z = fmaxf(fmaf(x.z * w.z, y.z, bm.z), 0.f);
    r.w = fmaxf(fmaf(x.w * w.w, y.w, bm.w), 0.f);
    return r;
}

struct PathSmem {
    float sW[3 * EMB];
    float sB[3 * EMB];
    float sAcc[8][256];
    float sCnt[8];
};

// ── paths kernel: exact R4 version (best measured; do not touch) ────────
template<int L>
__device__ __forceinline__ void path_body(
    PathSmem& sm,
    const int*   __restrict__ ents,
    const int*   __restrict__ mids,
    const float* __restrict__ counts,
    const float* __restrict__ E,
    const float* __restrict__ Wm,
    const float* __restrict__ Bm,
    int gofs)
{
    const int b    = blockIdx.x;
    const int tid  = threadIdx.x;
    const int wid  = tid >> 5;
    const int lane = tid & 31;

    for (int i = tid; i < 3 * EMB; i += 256) { sm.sW[i] = Wm[i]; sm.sB[i] = Bm[i]; }
    __syncthreads();

    int   e[4][L + 1];
    int   m[4][L];
    float cnt[4];
    #pragma unroll
    for (int pp = 0; pp < 4; pp++) {
        const long base = (long)b * PSZ + (wid + pp * 8);
        const int* ep = ents + base * (L + 1);
        const int* mp = mids + base * L;
        #pragma unroll
        for (int i = 0; i <= L; i++) e[pp][i] = ep[i];
        #pragma unroll
        for (int i = 0; i < L; i++)  m[pp][i] = mp[i];
        cnt[pp] = counts[base];
    }

    float4 a1 = make_float4(0.f, 0.f, 0.f, 0.f);
    float4 a2 = make_float4(0.f, 0.f, 0.f, 0.f);
    float  cs = 0.f;

    float4 buf[2][L + 1];
    #pragma unroll
    for (int i = 0; i <= L; i++)
        buf[0][i] = *(const float4*)(E + (long)e[0][i] * EMB + lane * 4);

    #pragma unroll
    for (int pp = 0; pp < 4; pp++) {
        if (pp < 3) {
            #pragma unroll
            for (int i = 0; i <= L; i++)
                buf[(pp + 1) & 1][i] =
                    *(const float4*)(E + (long)e[pp + 1][i] * EMB + lane * 4);
        }
        float4 (&rows)[L + 1] = buf[pp & 1];

        float4 x = rows[0];
        #pragma unroll
        for (int i = 0; i < L; i++) {
            float4 w  = *(const float4*)(sm.sW + m[pp][i] * EMB + lane * 4);
            float4 bb = *(const float4*)(sm.sB + m[pp][i] * EMB + lane * 4);
            x = relu_step(x, w, rows[i + 1], bb);
        }
        const float4 o1 = x;

        const float4 yl = rows[L];
        x = yl;
        #pragma unroll
        for (int i = L - 1; i >= 0; i--) {
            float4 w  = *(const float4*)(sm.sW + m[pp][i] * EMB + lane * 4);
            float4 bb = *(const float4*)(sm.sB + m[pp][i] * EMB + lane * 4);
            x = relu_step(x, w, yl, bb);
        }

        const float c0 = cnt[pp];
        a1.x += c0 * o1.x; a1.y += c0 * o1.y; a1.z += c0 * o1.z; a1.w += c0 * o1.w;
        a2.x += c0 * x.x;  a2.y += c0 * x.y;  a2.z += c0 * x.z;  a2.w += c0 * x.w;
        cs   += c0;
    }

    ((float4*)sm.sAcc[wid])[lane]         = a1;
    ((float4*)(sm.sAcc[wid] + 128))[lane] = a2;
    if (lane == 0) sm.sCnt[wid] = cs;
    __syncthreads();

    float s = 0.f, csum = 0.f;
    #pragma unroll
    for (int w = 0; w < 8; w++) { s += sm.sAcc[w][tid]; csum += sm.sCnt[w]; }
    g_H[(long)b * HDIM + gofs + tid] = s / csum;
}

__global__ __launch_bounds__(256) void paths_kernel(
    const int* __restrict__ ent1, const int* __restrict__ mid1, const float* __restrict__ c1,
    const int* __restrict__ ent2, const int* __restrict__ mid2, const float* __restrict__ c2,
    const int* __restrict__ ent3, const int* __restrict__ mid3, const float* __restrict__ c3,
    const float* __restrict__ E, const float* __restrict__ Wm, const float* __restrict__ Bm)
{
    __shared__ PathSmem sm;
    const int g = blockIdx.y;
    if (g == 0)      path_body<1>(sm, ent1, mid1, c1, E, Wm, Bm, 0);
    else if (g == 1) path_body<2>(sm, ent2, mid2, c2, E, Wm, Bm, 256);
    else             path_body<3>(sm, ent3, mid3, c3, E, Wm, Bm, 512);
}

// ── tf32 helpers ────────────────────────────────────────────────────────
__device__ __forceinline__ float totf32(float x) {
    unsigned int u;
    asm("cvt.rna.tf32.f32 %0, %1;" : "=r"(u) : "f"(x));
    return __uint_as_float(u);
}

__device__ __forceinline__ void mma_tf32(float c[4],
    unsigned int a0, unsigned int a1, unsigned int a2, unsigned int a3,
    unsigned int b0, unsigned int b1)
{
    asm volatile(
        "mma.sync.aligned.m16n8k8.row.col.f32.tf32.tf32.f32 "
        "{%0,%1,%2,%3}, {%4,%5,%6,%7}, {%8,%9}, {%0,%1,%2,%3};"
        : "+f"(c[0]), "+f"(c[1]), "+f"(c[2]), "+f"(c[3])
        : "r"(a0), "r"(a1), "r"(a2), "r"(a3), "r"(b0), "r"(b1));
}

// One-time W1 -> tf32-rounded copy (96 blocks x 256 thr, 1 float4 each)
__global__ void w1cvt_kernel(const float* __restrict__ W1) {
    const int i = blockIdx.x * 256 + threadIdx.x;     // 0..24575 float4s
    float4 v = ((const float4*)W1)[i];
    v.x = totf32(v.x); v.y = totf32(v.y); v.z = totf32(v.z); v.w = totf32(v.w);
    ((float4*)g_W1c)[i] = v;
}

// ────────────────────────────────────────────────────────────────────────
// MLP head, tensor-core v2: 256 blocks x 16 rows, 256 threads.
// A tile (16x768, tf32-rounded) staged ONCE in smem, padded stride 772
//   -> A-fragment LDS banks (4*gid+tig)%32 all distinct, conflict-free.
// B fragments loaded directly from g_W1c in L2 (4 full 32B sectors per
//   warp-LDG; W1c reused by all 256 blocks). No W smem, no k-chunk syncs.
// Warp w owns output cols [16w,16w+16) as 2 n-tiles. Layers 2/3 fp32.
// ────────────────────────────────────────────────────────────────────────
#define ASTRIDE 772
#define SB_F    164
#define MLP_SMEM_F (SB_F + MBLK * ASTRIDE)     // 164 + 12352 = 12516 floats

extern __shared__ float dsm[];

__global__ __launch_bounds__(256) void mlp_kernel(
    const float* __restrict__ b1,
    const float* __restrict__ W2, const float* __restrict__ b2,
    const float* __restrict__ W3, const float* __restrict__ b3,
    float* __restrict__ out)
{
    float* const sb1 = dsm;            // [128]
    float* const sb2 = dsm + 128;      // [32]
    float* const sb3 = dsm + 160;      // [1]
    float* const sA  = dsm + SB_F;     // [16][772]

    const int b0   = blockIdx.x * MBLK;
    const int tid  = threadIdx.x;
    const int lane = tid & 31;
    const int wrp  = tid >> 5;         // 0..7 -> cols [16w, 16w+16)
    const int gid  = lane >> 2;        // 0..7
    const int tig  = lane & 3;         // 0..3

    if (tid < 128) sb1[tid] = b1[tid];
    if (tid < 32)  sb2[tid] = b2[tid];
    if (tid == 0)  sb3[0]   = b3[0];

    // ── Stage A tile once (whole K), tf32-rounded ───────────────────────
    #pragma unroll
    for (int j = 0; j < 12; j++) {
        const int idx = tid + j * 256;          // 0..3071 float4s
        const int row = idx / 192, c4 = idx % 192;
        float4 v = *(const float4*)(g_H + (long)(b0 + row) * HDIM + c4 * 4);
        v.x = totf32(v.x); v.y = totf32(v.y); v.z = totf32(v.z); v.w = totf32(v.w);
        *(float4*)(sA + row * ASTRIDE + c4 * 4) = v;   // 772%4==0 -> aligned
    }
    __syncthreads();

    // ── Phase A: 96 k-chunks of 8, A from smem, B from g_W1c (L2) ───────
    float acc[2][4];
    #pragma unroll
    for (int nt = 0; nt < 2; nt++)
        #pragma unroll
        for (int i = 0; i < 4; i++) acc[nt][i] = 0.f;

    const float* const apBase = sA + gid * ASTRIDE + tig;
    const float* const bpBase = g_W1c + tig * 128 + wrp * 16 + gid;

    #pragma unroll 4
    for (int kk = 0; kk < 96; kk++) {
        const float* ap = apBase + kk * 8;
        const unsigned int A0 = __float_as_uint(ap[0]);
        const unsigned int A1 = __float_as_uint(ap[8 * ASTRIDE]);
        const unsigned int A2 = __float_as_uint(ap[4]);
        const unsigned int A3 = __float_as_uint(ap[8 * ASTRIDE + 4]);
        const float* bp = bpBase + kk * 8 * 128;
        #pragma unroll
        for (int nt = 0; nt < 2; nt++) {
            const unsigned int B0 = __float_as_uint(__ldg(bp + nt * 8));
            const unsigned int B1 = __float_as_uint(__ldg(bp + nt * 8 + 4 * 128));
            mma_tf32(acc[nt], A0, A1, A2, A3, B0, B1);
        }
    }
    __syncthreads();                   // all reads of sA done

    // ── Epilogue: bias + relu -> sh1 [16][132] (overlays sA) ────────────
    float* const sh1 = sA;
    float* const sh2 = sA + MBLK * 132;       // [16][33]
    #pragma unroll
    for (int nt = 0; nt < 2; nt++) {
        const int n0 = wrp * 16 + nt * 8 + tig * 2;
        sh1[gid * 132 + n0]           = fmaxf(acc[nt][0] + sb1[n0],     0.f);
        sh1[gid * 132 + n0 + 1]       = fmaxf(acc[nt][1] + sb1[n0 + 1], 0.f);
        sh1[(gid + 8) * 132 + n0]     = fmaxf(acc[nt][2] + sb1[n0],     0.f);
        sh1[(gid + 8) * 132 + n0 + 1] = fmaxf(acc[nt][3] + sb1[n0 + 1], 0.f);
    }
    __syncthreads();

    // ── Phase B: h2 = relu(h1 @ W2 + b2), [16,32] fp32 ──────────────────
    {
        const int r  = tid >> 4;              // 0..15
        const int cb = (tid & 15) * 2;        // 0,2,...,30
        float a0 = sb2[cb], a1 = sb2[cb + 1];
        #pragma unroll 8
        for (int k = 0; k < 128; k++) {
            const float  h = sh1[r * 132 + k];
            const float2 w = *(const float2*)(W2 + k * 32 + cb);
            a0 = fmaf(h, w.x, a0);
            a1 = fmaf(h, w.y, a1);
        }
        sh2[r * 33 + cb]     = fmaxf(a0, 0.f);
        sh2[r * 33 + cb + 1] = fmaxf(a1, 0.f);
    }
    __syncthreads();

    // ── Phase C: out = h2 @ W3 + b3, [16,1] fp32 ────────────────────────
    if (tid < MBLK) {
        float a = sb3[0];
        #pragma unroll
        for (int k = 0; k < 32; k++) a = fmaf(sh2[tid * 33 + k], W3[k], a);
        out[b0 + tid] = a;
    }
}

extern "C" void kernel_launch(void* const* d_in, const int* in_sizes, int n_in,
                              void* d_out, int out_size)
{
    const bool dictOrder = (in_sizes[2] == BSZ * PSZ);

    const int *ent1, *mid1, *ent2, *mid2, *ent3, *mid3;
    const float *c1, *c2, *c3;
    if (dictOrder) {
        ent1 = (const int*)d_in[0]; mid1 = (const int*)d_in[1]; c1 = (const float*)d_in[2];
        ent2 = (const int*)d_in[3]; mid2 = (const int*)d_in[4]; c2 = (const float*)d_in[5];
        ent3 = (const int*)d_in[6]; mid3 = (const int*)d_in[7]; c3 = (const float*)d_in[8];
    } else {
        ent1 = (const int*)d_in[0]; mid1 = (const int*)d_in[1];
        ent2 = (const int*)d_in[2]; mid2 = (const int*)d_in[3];
        ent3 = (const int*)d_in[4]; mid3 = (const int*)d_in[5];
        c1 = (const float*)d_in[6]; c2 = (const float*)d_in[7]; c3 = (const float*)d_in[8];
    }
    const float* E  = (const float*)d_in[9];
    const float* Wm = (const float*)d_in[10];
    const float* Bm = (const float*)d_in[11];
    const float* W1 = (const float*)d_in[12];
    const float* b1 = (const float*)d_in[13];
    const float* W2 = (const float*)d_in[14];
    const float* b2 = (const float*)d_in[15];
    const float* W3 = (const float*)d_in[16];
    const float* b3 = (const float*)d_in[17];

    const int mlpSmem = MLP_SMEM_F * sizeof(float);   // 50064 B
    cudaFuncSetAttribute(mlp_kernel, cudaFuncAttributeMaxDynamicSharedMemorySize,
                         mlpSmem);

    // One-time tf32 conversion of W1 (overlaps nothing; ~2 µs)
    w1cvt_kernel<<<(HDIM * 128 / 4) / 256, 256>>>(W1);

    dim3 pgrid(BSZ, 3);
    paths_kernel<<<pgrid, 256>>>(ent1, mid1, c1, ent2, mid2, c2, ent3, mid3, c3,
                                 E, Wm, Bm);
    mlp_kernel<<<BSZ / MBLK, 256, mlpSmem>>>(b1, W2, b2, W3, b3, (float*)d_out);
}